// round 1
// baseline (speedup 1.0000x reference)
#include <cuda_runtime.h>
#include <math.h>

// ---------------------------------------------------------------------------
// Mamba block forward.  Sizes fixed by the problem:
//   B=2, L=2048, d_model=1024, d_inner=2048, d_state=16, dt_rank=64, d_conv=4
// ---------------------------------------------------------------------------
#define LSEQ   2048
#define BATCH  2
#define DM     1024
#define DI     2048
#define NST    16
#define DTR    64
#define MROWS  (BATCH * LSEQ)   // 4096
#define NPROJ  96               // dt_rank + 2*d_state

// ------------------------- scratch (static device mem) ---------------------
__device__ float g_xr[(size_t)MROWS * (2 * DI)];   // in-proj output (xin|res)   64 MB
__device__ float g_u[(size_t)MROWS * DI];          // silu(conv(xin))            32 MB
__device__ float g_xdbl[(size_t)MROWS * NPROJ];    // u @ W_x                   1.5 MB
__device__ float g_delta[(size_t)MROWS * DI];      // softplus(dlt@W_dt + b)     32 MB
__device__ float g_y[(size_t)MROWS * DI];          // fused scan output          32 MB

// ------------------------- helpers ------------------------------------------
__device__ __forceinline__ float fast_ex2(float x) {
    float y;
    asm("ex2.approx.f32 %0, %1;" : "=f"(y) : "f"(x));
    return y;
}

// ============================================================================
// Kernel 1/6: generic 128x128x16 SGEMM, C = A(MxK) * B(KxN), all row-major.
// Requires M%128==0, N%128==0, K%16==0.  256 threads, 8x8 per thread.
// ============================================================================
__global__ __launch_bounds__(256) void sgemm_kernel(
    int M, int N, int K,
    const float* __restrict__ A, const float* __restrict__ B,
    float* __restrict__ C)
{
    __shared__ float As[16][128];   // transposed A tile
    __shared__ float Bs[16][128];

    const int tid  = threadIdx.x;
    const int brow = blockIdx.y * 128;
    const int bcol = blockIdx.x * 128;

    const int aRow  = tid >> 2;          // 0..63   (x2 passes)
    const int aCol  = (tid & 3) * 4;     // 0,4,8,12
    const int bRow  = tid >> 5;          // 0..7    (x2 passes)
    const int bCol  = (tid & 31) * 4;    // 0..124

    const int trow = (tid >> 4) * 8;
    const int tcol = (tid & 15) * 8;

    float acc[8][8];
#pragma unroll
    for (int i = 0; i < 8; i++)
#pragma unroll
        for (int j = 0; j < 8; j++) acc[i][j] = 0.f;

    const float* Aptr = A + (size_t)brow * K;
    const float* Bptr = B + bcol;

    for (int k0 = 0; k0 < K; k0 += 16) {
#pragma unroll
        for (int i = 0; i < 2; i++) {
            float4 v = *(const float4*)&Aptr[(size_t)(aRow + i * 64) * K + k0 + aCol];
            As[aCol + 0][aRow + i * 64] = v.x;
            As[aCol + 1][aRow + i * 64] = v.y;
            As[aCol + 2][aRow + i * 64] = v.z;
            As[aCol + 3][aRow + i * 64] = v.w;
        }
#pragma unroll
        for (int i = 0; i < 2; i++) {
            float4 v = *(const float4*)&Bptr[(size_t)(k0 + bRow + i * 8) * N + bCol];
            *(float4*)&Bs[bRow + i * 8][bCol] = v;
        }
        __syncthreads();

#pragma unroll
        for (int k = 0; k < 16; k++) {
            float4 a0 = *(const float4*)&As[k][trow];
            float4 a1 = *(const float4*)&As[k][trow + 4];
            float4 b0 = *(const float4*)&Bs[k][tcol];
            float4 b1 = *(const float4*)&Bs[k][tcol + 4];
            float ra[8] = {a0.x, a0.y, a0.z, a0.w, a1.x, a1.y, a1.z, a1.w};
            float rb[8] = {b0.x, b0.y, b0.z, b0.w, b1.x, b1.y, b1.z, b1.w};
#pragma unroll
            for (int i = 0; i < 8; i++)
#pragma unroll
                for (int j = 0; j < 8; j++) acc[i][j] += ra[i] * rb[j];
        }
        __syncthreads();
    }

    float* Cptr = C + (size_t)brow * N + bcol;
#pragma unroll
    for (int i = 0; i < 8; i++) {
#pragma unroll
        for (int j = 0; j < 8; j += 4) {
            float4 v = make_float4(acc[i][j], acc[i][j + 1], acc[i][j + 2], acc[i][j + 3]);
            *(float4*)&Cptr[(size_t)(trow + i) * N + tcol + j] = v;
        }
    }
}

// ============================================================================
// Kernel 2/6: causal depthwise conv1d (K=4) + bias + silu.  xin -> u
// ============================================================================
__global__ __launch_bounds__(256) void conv_silu_kernel(
    const float* __restrict__ cw,   // (DI, 1, 4)
    const float* __restrict__ cb)   // (DI,)
{
    int idx = blockIdx.x * 256 + threadIdx.x;      // over MROWS*DI
    int d   = idx & (DI - 1);
    int row = idx >> 11;                            // b*L + t
    int t   = row & (LSEQ - 1);

    float acc = cb[d];
#pragma unroll
    for (int k = 0; k < 4; k++) {
        int tt = t - 3 + k;
        if (tt >= 0)
            acc += __ldg(&cw[d * 4 + k]) * g_xr[(size_t)(row - 3 + k) * (2 * DI) + d];
    }
    g_u[idx] = acc / (1.f + expf(-acc));
}

// ============================================================================
// Kernel 3/6: x_dbl = u @ W_x   (4096 x 2048 x 96).  64 rows/block.
// ============================================================================
__global__ __launch_bounds__(256) void gemm_xdbl_kernel(const float* __restrict__ Wx)
{
    __shared__ float As[16][64];
    __shared__ float Bs[16][NPROJ];

    const int tid  = threadIdx.x;
    const int brow = blockIdx.x * 64;

    const int ar = tid >> 2;           // 0..63
    const int ak = (tid & 3) * 4;      // 0,4,8,12
    const int trow = (tid >> 4) * 4;   // 0..60
    const int tcol = (tid & 15) * 6;   // 0..90

    float acc[4][6];
#pragma unroll
    for (int i = 0; i < 4; i++)
#pragma unroll
        for (int j = 0; j < 6; j++) acc[i][j] = 0.f;

    for (int k0 = 0; k0 < DI; k0 += 16) {
        {
            float4 v = *(const float4*)&g_u[(size_t)(brow + ar) * DI + k0 + ak];
            As[ak + 0][ar] = v.x;
            As[ak + 1][ar] = v.y;
            As[ak + 2][ar] = v.z;
            As[ak + 3][ar] = v.w;
        }
#pragma unroll
        for (int i = 0; i < 6; i++) {
            int idx = tid + i * 256;          // 1536 = 16 * 96
            int r = idx / NPROJ;
            int c = idx - r * NPROJ;
            Bs[r][c] = Wx[(size_t)(k0 + r) * NPROJ + c];
        }
        __syncthreads();

#pragma unroll
        for (int k = 0; k < 16; k++) {
            float ra[4], rb[6];
#pragma unroll
            for (int i = 0; i < 4; i++) ra[i] = As[k][trow + i];
#pragma unroll
            for (int j = 0; j < 6; j++) rb[j] = Bs[k][tcol + j];
#pragma unroll
            for (int i = 0; i < 4; i++)
#pragma unroll
                for (int j = 0; j < 6; j++) acc[i][j] += ra[i] * rb[j];
        }
        __syncthreads();
    }

#pragma unroll
    for (int i = 0; i < 4; i++)
#pragma unroll
        for (int j = 0; j < 6; j++)
            g_xdbl[(size_t)(brow + trow + i) * NPROJ + tcol + j] = acc[i][j];
}

// ============================================================================
// Kernel 4/6: delta = softplus(x_dbl[:, :64] @ W_dt + b_dt)
//   M=4096, K=64, N=2048.  8 rows x 2048 cols per block, 256 threads.
// ============================================================================
__global__ __launch_bounds__(256) void delta_kernel(
    const float* __restrict__ Wdt,  // (64, 2048)
    const float* __restrict__ bdt)  // (2048,)
{
    __shared__ float sd[8][DTR];
    const int tid  = threadIdx.x;
    const int brow = blockIdx.x * 8;

#pragma unroll
    for (int i = 0; i < 2; i++) {
        int idx = tid + i * 256;        // 512 = 8 * 64
        int r = idx >> 6, c = idx & 63;
        sd[r][c] = g_xdbl[(size_t)(brow + r) * NPROJ + c];
    }
    __syncthreads();

    float acc[8][8];
#pragma unroll
    for (int m = 0; m < 8; m++)
#pragma unroll
        for (int j = 0; j < 8; j++) acc[m][j] = 0.f;

    for (int k = 0; k < DTR; k++) {
        float w[8];
#pragma unroll
        for (int j = 0; j < 8; j++) w[j] = __ldg(&Wdt[(size_t)k * DI + tid + j * 256]);
#pragma unroll
        for (int m = 0; m < 8; m++) {
            float dv = sd[m][k];
#pragma unroll
            for (int j = 0; j < 8; j++) acc[m][j] += dv * w[j];
        }
    }

#pragma unroll
    for (int j = 0; j < 8; j++) {
        int col = tid + j * 256;
        float bb = bdt[col];
#pragma unroll
        for (int m = 0; m < 8; m++) {
            float x = acc[m][j] + bb;
            float sp = (x > 20.f) ? x : log1pf(expf(x));
            g_delta[(size_t)(brow + m) * DI + col] = sp;
        }
    }
}

// ============================================================================
// Kernel 5/6: selective scan, fused with  y = (scan + u*D) * silu(res).
//   4 lanes per channel d (4 states each), shfl-xor reduce over the 16 states.
//   Block = 128 threads = 32 channels.  Grid = (DI/32, BATCH).
//   All time-series operands staged through SMEM in chunks of 64 steps so the
//   sequential critical path never touches an LDG.
// ============================================================================
#define TCHUNK 64
__global__ __launch_bounds__(128) void scan_kernel(
    const float* __restrict__ A_log,   // (DI, 16)
    const float* __restrict__ Dp)      // (DI,)
{
    __shared__ float sB[TCHUNK][NST];
    __shared__ float sC[TCHUNK][NST];
    __shared__ float sDt[TCHUNK][32];
    __shared__ float sU[TCHUNK][32];
    __shared__ float sR[TCHUNK][32];

    const int b    = blockIdx.y;
    const int tid  = threadIdx.x;
    const int dloc = tid >> 2;                // 0..31
    const int ng   = tid & 3;                 // state quad
    const int n0   = ng * 4;
    const int d0   = blockIdx.x * 32;
    const int d    = d0 + dloc;

    float a2[4], h[4];
#pragma unroll
    for (int i = 0; i < 4; i++) {
        a2[i] = -expf(A_log[(size_t)d * NST + n0 + i]) * 1.44269504f;  // A * log2(e)
        h[i] = 0.f;
    }
    const float Dv = Dp[d];

    for (int t0 = 0; t0 < LSEQ; t0 += TCHUNK) {
        // stage B, C (16 wide) and delta, u, res (32 channels) for this chunk
        for (int idx = tid; idx < TCHUNK * NST; idx += 128) {
            int tt = idx >> 4, n = idx & 15;
            size_t grow = (size_t)(b * LSEQ + t0 + tt) * NPROJ;
            sB[tt][n] = g_xdbl[grow + DTR + n];
            sC[tt][n] = g_xdbl[grow + DTR + NST + n];
        }
        for (int idx = tid; idx < TCHUNK * 32; idx += 128) {
            int tt = idx >> 5, dd = idx & 31;
            size_t base = (size_t)(b * LSEQ + t0 + tt) * DI + d0 + dd;
            sDt[tt][dd] = g_delta[base];
            sU[tt][dd]  = g_u[base];
            sR[tt][dd]  = g_xr[(size_t)(b * LSEQ + t0 + tt) * (2 * DI) + DI + d0 + dd];
        }
        __syncthreads();

        for (int tt = 0; tt < TCHUNK; tt++) {
            float dt_v = sDt[tt][dloc];
            float u_v  = sU[tt][dloc];
            float du   = dt_v * u_v;
            float yp = 0.f;
#pragma unroll
            for (int i = 0; i < 4; i++) {
                h[i] = fast_ex2(dt_v * a2[i]) * h[i] + du * sB[tt][n0 + i];
                yp += h[i] * sC[tt][n0 + i];
            }
            yp += __shfl_xor_sync(0xffffffffu, yp, 1);
            yp += __shfl_xor_sync(0xffffffffu, yp, 2);
            if (ng == 0) {
                float res = sR[tt][dloc];
                float sil = res / (1.f + expf(-res));
                g_y[(size_t)(b * LSEQ + t0 + tt) * DI + d] = (yp + u_v * Dv) * sil;
            }
        }
        __syncthreads();
    }
}

// ============================================================================
// launch
// ============================================================================
extern "C" void kernel_launch(void* const* d_in, const int* in_sizes, int n_in,
                              void* d_out, int out_size)
{
    const float* x      = (const float*)d_in[0];
    const float* W_in   = (const float*)d_in[1];
    const float* conv_w = (const float*)d_in[2];
    const float* conv_b = (const float*)d_in[3];
    const float* W_x    = (const float*)d_in[4];
    const float* W_dt   = (const float*)d_in[5];
    const float* b_dt   = (const float*)d_in[6];
    const float* A_log  = (const float*)d_in[7];
    const float* Dp     = (const float*)d_in[8];
    const float* W_out  = (const float*)d_in[9];
    float* out          = (float*)d_out;

    float *p_xr, *p_y;
    cudaGetSymbolAddress((void**)&p_xr, g_xr);
    cudaGetSymbolAddress((void**)&p_y,  g_y);

    // 1. in-projection: (4096 x 1024) @ (1024 x 4096)
    sgemm_kernel<<<dim3(4096 / 128, MROWS / 128), 256>>>(MROWS, 2 * DI, DM, x, W_in, p_xr);

    // 2. causal depthwise conv + silu
    conv_silu_kernel<<<(MROWS * DI) / 256, 256>>>(conv_w, conv_b);

    // 3. x_dbl = u @ W_x
    gemm_xdbl_kernel<<<MROWS / 64, 256>>>(W_x);

    // 4. delta = softplus(dlt @ W_dt + b_dt)
    delta_kernel<<<MROWS / 8, 256>>>(W_dt, b_dt);

    // 5. selective scan + gating epilogue (fused)
    scan_kernel<<<dim3(DI / 32, BATCH), 128>>>(A_log, Dp);

    // 6. out-projection: (4096 x 2048) @ (2048 x 1024)
    sgemm_kernel<<<dim3(DM / 128, MROWS / 128), 256>>>(MROWS, DM, DI, p_y, W_out, out);
}

// round 4
// speedup vs baseline: 1.3179x; 1.3179x over previous
#include <cuda_runtime.h>
#include <stdint.h>
#include <math.h>

// ---------------------------------------------------------------------------
// Mamba block forward.  B=2, L=2048, d_model=1024, d_inner=2048,
// d_state=16, dt_rank=64, d_conv=4
// ---------------------------------------------------------------------------
#define LSEQ   2048
#define BATCH  2
#define DM     1024
#define DI     2048
#define NST    16
#define DTR    64
#define MROWS  (BATCH * LSEQ)   // 4096
#define NPROJ  96               // dt_rank + 2*d_state

// ------------------------- scratch (static device mem) ---------------------
__device__ float g_xr[(size_t)MROWS * (2 * DI)];   // in-proj output (xin|res)
__device__ float g_u[(size_t)MROWS * DI];          // silu(conv(xin))
__device__ float g_xdbl[(size_t)MROWS * NPROJ];    // u @ W_x
__device__ float g_delta[(size_t)MROWS * DI];      // softplus(dlt@W_dt + b)
__device__ float g_y[(size_t)MROWS * DI];          // fused scan output

// ------------------------- helpers ------------------------------------------
__device__ __forceinline__ float fast_ex2(float x) {
    float y;
    asm("ex2.approx.f32 %0, %1;" : "=f"(y) : "f"(x));
    return y;
}

__device__ __forceinline__ void cp_async16(uint32_t saddr, const void* gptr) {
    asm volatile("cp.async.cg.shared.global [%0], [%1], 16;\n" :: "r"(saddr), "l"(gptr));
}
__device__ __forceinline__ void cp_commit() {
    asm volatile("cp.async.commit_group;\n");
}
template <int NWAIT> __device__ __forceinline__ void cp_wait() {
    asm volatile("cp.async.wait_group %0;\n" :: "n"(NWAIT));
}

// split fp32 into tf32 hi + residual lo (3xTF32 error compensation)
__device__ __forceinline__ void split_tf32(float v, uint32_t& hi, uint32_t& lo) {
    uint32_t h = __float_as_uint(v) & 0xFFFFE000u;
    hi = h;
    lo = __float_as_uint(v - __uint_as_float(h));
}

// ============================================================================
// 3xTF32 tensor-core GEMM: C = A(MxK, row stride lda) @ B(KxN row-major).
// 128x128x32 CTA tile, 8 warps (2x4), 64x32 warp tile, m16n8k8 tf32 mma.
// Each product computed as ahi*bhi + alo*bhi + ahi*blo  (fp32-grade accuracy).
// 2-stage cp.async double buffer.  epi: 0 = plain store, 1 = softplus(c+bias).
// ============================================================================
#define BM 128
#define BN 128
#define BK 32
#define AS_STRIDE 36     // BK + 4 pad  -> conflict-free A frag loads
#define BS_STRIDE 136    // BN + 8 pad  -> conflict-free B frag loads
#define AS_FLOATS (BM * AS_STRIDE)             // 4608
#define BS_FLOATS (BK * BS_STRIDE)             // 4352
#define STAGE_FLOATS (AS_FLOATS + BS_FLOATS)   // 8960
#define SMEM_BYTES (2 * STAGE_FLOATS * 4)      // 71680

extern __shared__ float smem_dyn[];

__device__ __forceinline__ void load_tile(
    const float* __restrict__ A, const float* __restrict__ B,
    int lda, int N, int brow, int bcol, int k0,
    float* As, float* Bs, int tid)
{
#pragma unroll
    for (int i = 0; i < 4; i++) {              // A: 128 rows x 8 chunks(16B)
        int ch = tid + i * 256;
        int r = ch >> 3, cc = ch & 7;
        const float* g = A + (size_t)(brow + r) * lda + k0 + cc * 4;
        uint32_t s = (uint32_t)__cvta_generic_to_shared(As + r * AS_STRIDE + cc * 4);
        cp_async16(s, g);
    }
#pragma unroll
    for (int i = 0; i < 4; i++) {              // B: 32 rows x 32 chunks(16B)
        int ch = tid + i * 256;
        int r = ch >> 5, cc = ch & 31;
        const float* g = B + (size_t)(k0 + r) * N + bcol + cc * 4;
        uint32_t s = (uint32_t)__cvta_generic_to_shared(Bs + r * BS_STRIDE + cc * 4);
        cp_async16(s, g);
    }
}

#define MMA_TF32(ACC, A0, A1, A2, A3, B0, B1)                                  \
    asm volatile(                                                              \
        "mma.sync.aligned.m16n8k8.row.col.f32.tf32.tf32.f32 "                  \
        "{%0,%1,%2,%3}, {%4,%5,%6,%7}, {%8,%9}, {%0,%1,%2,%3};\n"              \
        : "+f"(ACC[0]), "+f"(ACC[1]), "+f"(ACC[2]), "+f"(ACC[3])               \
        : "r"(A0), "r"(A1), "r"(A2), "r"(A3), "r"(B0), "r"(B1))

__global__ __launch_bounds__(256) void mma_gemm_kernel(
    int M, int N, int K, int lda,
    const float* __restrict__ A, const float* __restrict__ B,
    float* __restrict__ C,
    const float* __restrict__ bias, int epi)
{
    const int tid  = threadIdx.x;
    const int wid  = tid >> 5;
    const int lane = tid & 31;
    const int wm   = (wid >> 2) * 64;   // warp row offset in CTA tile
    const int wn   = (wid & 3) * 32;    // warp col offset
    const int brow = blockIdx.y * BM;
    const int bcol = blockIdx.x * BN;

    float* As0 = smem_dyn;
    float* Bs0 = smem_dyn + AS_FLOATS;
    float* As1 = smem_dyn + STAGE_FLOATS;
    float* Bs1 = smem_dyn + STAGE_FLOATS + AS_FLOATS;

    float acc[4][4][4];
#pragma unroll
    for (int mi = 0; mi < 4; mi++)
#pragma unroll
        for (int ni = 0; ni < 4; ni++)
#pragma unroll
            for (int c = 0; c < 4; c++) acc[mi][ni][c] = 0.f;

    const int KT = K / BK;

    load_tile(A, B, lda, N, brow, bcol, 0, As0, Bs0, tid);
    cp_commit();

    const int fr = lane >> 2;      // 0..7
    const int fc = lane & 3;       // 0..3

    for (int kt = 0; kt < KT; kt++) {
        float* Ac = (kt & 1) ? As1 : As0;
        float* Bc = (kt & 1) ? Bs1 : Bs0;
        if (kt + 1 < KT) {
            float* An = (kt & 1) ? As0 : As1;
            float* Bn = (kt & 1) ? Bs0 : Bs1;
            load_tile(A, B, lda, N, brow, bcol, (kt + 1) * BK, An, Bn, tid);
            cp_commit();
            cp_wait<1>();
        } else {
            cp_wait<0>();
        }
        __syncthreads();

#pragma unroll
        for (int kk = 0; kk < 4; kk++) {
            const int k = kk * 8;
            uint32_t ah[4][4], al[4][4], bh[4][2], bl[4][2];
#pragma unroll
            for (int mi = 0; mi < 4; mi++) {
                int rb = wm + mi * 16 + fr;
                split_tf32(Ac[rb * AS_STRIDE + k + fc],           ah[mi][0], al[mi][0]);
                split_tf32(Ac[(rb + 8) * AS_STRIDE + k + fc],     ah[mi][1], al[mi][1]);
                split_tf32(Ac[rb * AS_STRIDE + k + fc + 4],       ah[mi][2], al[mi][2]);
                split_tf32(Ac[(rb + 8) * AS_STRIDE + k + fc + 4], ah[mi][3], al[mi][3]);
            }
#pragma unroll
            for (int ni = 0; ni < 4; ni++) {
                int cb = wn + ni * 8 + fr;
                split_tf32(Bc[(k + fc) * BS_STRIDE + cb],     bh[ni][0], bl[ni][0]);
                split_tf32(Bc[(k + fc + 4) * BS_STRIDE + cb], bh[ni][1], bl[ni][1]);
            }
#pragma unroll
            for (int mi = 0; mi < 4; mi++)
#pragma unroll
                for (int ni = 0; ni < 4; ni++) {
                    MMA_TF32(acc[mi][ni], al[mi][0], al[mi][1], al[mi][2], al[mi][3],
                             bh[ni][0], bh[ni][1]);
                    MMA_TF32(acc[mi][ni], ah[mi][0], ah[mi][1], ah[mi][2], ah[mi][3],
                             bl[ni][0], bl[ni][1]);
                    MMA_TF32(acc[mi][ni], ah[mi][0], ah[mi][1], ah[mi][2], ah[mi][3],
                             bh[ni][0], bh[ni][1]);
                }
        }
        __syncthreads();
    }

    // ------------------------------ epilogue -------------------------------
    const int erow = fr;             // lane/4
    const int ecol = fc * 2;         // (lane%4)*2
#pragma unroll
    for (int mi = 0; mi < 4; mi++) {
#pragma unroll
        for (int ni = 0; ni < 4; ni++) {
            int row = brow + wm + mi * 16 + erow;
            int col = bcol + wn + ni * 8 + ecol;
            if (epi == 0) {
                *(float2*)&C[(size_t)row * N + col] =
                    make_float2(acc[mi][ni][0], acc[mi][ni][1]);
                *(float2*)&C[(size_t)(row + 8) * N + col] =
                    make_float2(acc[mi][ni][2], acc[mi][ni][3]);
            } else {
                float b0 = bias[col], b1 = bias[col + 1];
                float v[4] = {acc[mi][ni][0] + b0, acc[mi][ni][1] + b1,
                              acc[mi][ni][2] + b0, acc[mi][ni][3] + b1};
#pragma unroll
                for (int q = 0; q < 4; q++)
                    v[q] = (v[q] > 20.f) ? v[q] : log1pf(expf(v[q]));
                *(float2*)&C[(size_t)row * N + col] = make_float2(v[0], v[1]);
                *(float2*)&C[(size_t)(row + 8) * N + col] = make_float2(v[2], v[3]);
            }
        }
    }
}

// ============================================================================
// causal depthwise conv1d (K=4) + bias + silu.  xin -> u
// ============================================================================
__global__ __launch_bounds__(256) void conv_silu_kernel(
    const float* __restrict__ cw, const float* __restrict__ cb)
{
    int idx = blockIdx.x * 256 + threadIdx.x;      // over MROWS*DI
    int d   = idx & (DI - 1);
    int row = idx >> 11;                            // b*L + t
    int t   = row & (LSEQ - 1);

    float acc = cb[d];
#pragma unroll
    for (int k = 0; k < 4; k++) {
        int tt = t - 3 + k;
        if (tt >= 0)
            acc += __ldg(&cw[d * 4 + k]) * g_xr[(size_t)(row - 3 + k) * (2 * DI) + d];
    }
    g_u[idx] = acc / (1.f + expf(-acc));
}

// ============================================================================
// x_dbl = u @ W_x   (4096 x 2048 x 96).  64 rows/block.
// ============================================================================
__global__ __launch_bounds__(256) void gemm_xdbl_kernel(const float* __restrict__ Wx)
{
    __shared__ float As[16][64];
    __shared__ float Bs[16][NPROJ];

    const int tid  = threadIdx.x;
    const int brow = blockIdx.x * 64;

    const int ar = tid >> 2;
    const int ak = (tid & 3) * 4;
    const int trow = (tid >> 4) * 4;
    const int tcol = (tid & 15) * 6;

    float acc[4][6];
#pragma unroll
    for (int i = 0; i < 4; i++)
#pragma unroll
        for (int j = 0; j < 6; j++) acc[i][j] = 0.f;

    for (int k0 = 0; k0 < DI; k0 += 16) {
        {
            float4 v = *(const float4*)&g_u[(size_t)(brow + ar) * DI + k0 + ak];
            As[ak + 0][ar] = v.x;
            As[ak + 1][ar] = v.y;
            As[ak + 2][ar] = v.z;
            As[ak + 3][ar] = v.w;
        }
#pragma unroll
        for (int i = 0; i < 6; i++) {
            int idx = tid + i * 256;
            int r = idx / NPROJ;
            int c = idx - r * NPROJ;
            Bs[r][c] = Wx[(size_t)(k0 + r) * NPROJ + c];
        }
        __syncthreads();

#pragma unroll
        for (int k = 0; k < 16; k++) {
            float ra[4], rb[6];
#pragma unroll
            for (int i = 0; i < 4; i++) ra[i] = As[k][trow + i];
#pragma unroll
            for (int j = 0; j < 6; j++) rb[j] = Bs[k][tcol + j];
#pragma unroll
            for (int i = 0; i < 4; i++)
#pragma unroll
                for (int j = 0; j < 6; j++) acc[i][j] += ra[i] * rb[j];
        }
        __syncthreads();
    }

#pragma unroll
    for (int i = 0; i < 4; i++)
#pragma unroll
        for (int j = 0; j < 6; j++)
            g_xdbl[(size_t)(brow + trow + i) * NPROJ + tcol + j] = acc[i][j];
}

// ============================================================================
// selective scan, fused with  y = (scan + u*D) * silu(res).
// ============================================================================
#define TCHUNK 64
__global__ __launch_bounds__(128) void scan_kernel(
    const float* __restrict__ A_log, const float* __restrict__ Dp)
{
    __shared__ float sB[TCHUNK][NST];
    __shared__ float sC[TCHUNK][NST];
    __shared__ float sDt[TCHUNK][32];
    __shared__ float sU[TCHUNK][32];
    __shared__ float sR[TCHUNK][32];

    const int b    = blockIdx.y;
    const int tid  = threadIdx.x;
    const int dloc = tid >> 2;
    const int ng   = tid & 3;
    const int n0   = ng * 4;
    const int d0   = blockIdx.x * 32;
    const int d    = d0 + dloc;

    float a2[4], h[4];
#pragma unroll
    for (int i = 0; i < 4; i++) {
        a2[i] = -expf(A_log[(size_t)d * NST + n0 + i]) * 1.44269504f;
        h[i] = 0.f;
    }
    const float Dv = Dp[d];

    for (int t0 = 0; t0 < LSEQ; t0 += TCHUNK) {
        for (int idx = tid; idx < TCHUNK * NST; idx += 128) {
            int tt = idx >> 4, n = idx & 15;
            size_t grow = (size_t)(b * LSEQ + t0 + tt) * NPROJ;
            sB[tt][n] = g_xdbl[grow + DTR + n];
            sC[tt][n] = g_xdbl[grow + DTR + NST + n];
        }
        for (int idx = tid; idx < TCHUNK * 32; idx += 128) {
            int tt = idx >> 5, dd = idx & 31;
            size_t base = (size_t)(b * LSEQ + t0 + tt) * DI + d0 + dd;
            sDt[tt][dd] = g_delta[base];
            sU[tt][dd]  = g_u[base];
            sR[tt][dd]  = g_xr[(size_t)(b * LSEQ + t0 + tt) * (2 * DI) + DI + d0 + dd];
        }
        __syncthreads();

        for (int tt = 0; tt < TCHUNK; tt++) {
            float dt_v = sDt[tt][dloc];
            float u_v  = sU[tt][dloc];
            float du   = dt_v * u_v;
            float yp = 0.f;
#pragma unroll
            for (int i = 0; i < 4; i++) {
                h[i] = fast_ex2(dt_v * a2[i]) * h[i] + du * sB[tt][n0 + i];
                yp += h[i] * sC[tt][n0 + i];
            }
            yp += __shfl_xor_sync(0xffffffffu, yp, 1);
            yp += __shfl_xor_sync(0xffffffffu, yp, 2);
            if (ng == 0) {
                float res = sR[tt][dloc];
                float sil = res / (1.f + expf(-res));
                g_y[(size_t)(b * LSEQ + t0 + tt) * DI + d] = (yp + u_v * Dv) * sil;
            }
        }
        __syncthreads();
    }
}

// ============================================================================
// launch
// ============================================================================
extern "C" void kernel_launch(void* const* d_in, const int* in_sizes, int n_in,
                              void* d_out, int out_size)
{
    const float* x      = (const float*)d_in[0];
    const float* W_in   = (const float*)d_in[1];
    const float* conv_w = (const float*)d_in[2];
    const float* conv_b = (const float*)d_in[3];
    const float* W_x    = (const float*)d_in[4];
    const float* W_dt   = (const float*)d_in[5];
    const float* b_dt   = (const float*)d_in[6];
    const float* A_log  = (const float*)d_in[7];
    const float* Dp     = (const float*)d_in[8];
    const float* W_out  = (const float*)d_in[9];
    float* out          = (float*)d_out;

    float *p_xr, *p_y, *p_xdbl, *p_delta;
    cudaGetSymbolAddress((void**)&p_xr,    g_xr);
    cudaGetSymbolAddress((void**)&p_y,     g_y);
    cudaGetSymbolAddress((void**)&p_xdbl,  g_xdbl);
    cudaGetSymbolAddress((void**)&p_delta, g_delta);

    cudaFuncSetAttribute(mma_gemm_kernel,
                         cudaFuncAttributeMaxDynamicSharedMemorySize, SMEM_BYTES);

    // 1. in-projection: (4096 x 1024) @ (1024 x 4096)
    mma_gemm_kernel<<<dim3((2 * DI) / BN, MROWS / BM), 256, SMEM_BYTES>>>(
        MROWS, 2 * DI, DM, DM, x, W_in, p_xr, nullptr, 0);

    // 2. causal depthwise conv + silu
    conv_silu_kernel<<<(MROWS * DI) / 256, 256>>>(conv_w, conv_b);

    // 3. x_dbl = u @ W_x
    gemm_xdbl_kernel<<<MROWS / 64, 256>>>(W_x);

    // 4. delta = softplus(x_dbl[:, :64] @ W_dt + b_dt)  (fused epilogue)
    mma_gemm_kernel<<<dim3(DI / BN, MROWS / BM), 256, SMEM_BYTES>>>(
        MROWS, DI, DTR, NPROJ, p_xdbl, W_dt, p_delta, b_dt, 1);

    // 5. selective scan + gating epilogue (fused)
    scan_kernel<<<dim3(DI / 32, BATCH), 128>>>(A_log, Dp);

    // 6. out-projection: (4096 x 2048) @ (2048 x 1024)
    mma_gemm_kernel<<<dim3(DM / BN, MROWS / BM), 256, SMEM_BYTES>>>(
        MROWS, DM, DI, DI, p_y, W_out, out, nullptr, 0);
}

// round 6
// speedup vs baseline: 1.6628x; 1.2617x over previous
#include <cuda_runtime.h>
#include <cuda_bf16.h>
#include <stdint.h>
#include <math.h>

// ---------------------------------------------------------------------------
// Mamba block forward.  B=2, L=2048, d_model=1024, d_inner=2048,
// d_state=16, dt_rank=64, d_conv=4
// ---------------------------------------------------------------------------
#define LSEQ   2048
#define BATCH  2
#define DM     1024
#define DI     2048
#define NST    16
#define DTR    64
#define MROWS  (BATCH * LSEQ)   // 4096
#define NPROJ  96               // dt_rank + 2*d_state

// ------------------------- scratch (static device mem) ---------------------
__device__ float g_xr[(size_t)MROWS * (2 * DI)];   // in-proj output (xin|res)
__device__ float g_u[(size_t)MROWS * DI];          // silu(conv(xin))
__device__ float g_xdbl[(size_t)MROWS * NPROJ];    // u @ W_x
__device__ float g_delta[(size_t)MROWS * DI];      // softplus(dlt@W_dt + b)
__device__ float g_y[(size_t)MROWS * DI];          // fused scan output

// bf16x3 expanded operands: A' = [ah|al|ah] (M x 3K),  B'^T = [bh|bh|bl] (N x 3K)
__device__ __align__(1024) __nv_bfloat16 g_xbf  [(size_t)MROWS * (3 * DM)];
__device__ __align__(1024) __nv_bfloat16 g_wibf [(size_t)(2 * DI) * (3 * DM)];
__device__ __align__(1024) __nv_bfloat16 g_ybf  [(size_t)MROWS * (3 * DI)];
__device__ __align__(1024) __nv_bfloat16 g_wobf [(size_t)DM * (3 * DI)];
__device__ __align__(1024) __nv_bfloat16 g_xdblbf[(size_t)MROWS * (3 * DTR)];
__device__ __align__(1024) __nv_bfloat16 g_wdtbf [(size_t)DI * (3 * DTR)];

// ------------------------- helpers ------------------------------------------
__device__ __forceinline__ float fast_ex2(float x) {
    float y;
    asm("ex2.approx.f32 %0, %1;" : "=f"(y) : "f"(x));
    return y;
}
__device__ __forceinline__ uint32_t smem_u32(const void* p) {
    uint32_t a;
    asm("{ .reg .u64 t; cvta.to.shared.u64 t, %1; cvt.u32.u64 %0, t; }" : "=r"(a) : "l"(p));
    return a;
}
__device__ __forceinline__ void cp_async16(uint32_t saddr, const void* gptr) {
    asm volatile("cp.async.cg.shared.global [%0], [%1], 16;\n" :: "r"(saddr), "l"(gptr));
}
__device__ __forceinline__ void cp_commit() {
    asm volatile("cp.async.commit_group;\n");
}
template <int NWAIT> __device__ __forceinline__ void cp_wait() {
    asm volatile("cp.async.wait_group %0;\n" :: "n"(NWAIT));
}

#define LDSM_X4(r, addr)                                                       \
    asm volatile("ldmatrix.sync.aligned.m8n8.x4.shared.b16 {%0,%1,%2,%3}, [%4];" \
                 : "=r"((r)[0]), "=r"((r)[1]), "=r"((r)[2]), "=r"((r)[3])      \
                 : "r"(addr))

#define MMA_BF16(ACC, Aq, B0, B1)                                              \
    asm volatile(                                                              \
        "mma.sync.aligned.m16n8k16.row.col.f32.bf16.bf16.f32 "                 \
        "{%0,%1,%2,%3}, {%4,%5,%6,%7}, {%8,%9}, {%0,%1,%2,%3};\n"              \
        : "+f"(ACC[0]), "+f"(ACC[1]), "+f"(ACC[2]), "+f"(ACC[3])               \
        : "r"((Aq)[0]), "r"((Aq)[1]), "r"((Aq)[2]), "r"((Aq)[3]),              \
          "r"(B0), "r"(B1))

// ============================================================================
// bf16 tensor-core GEMM:  C(MxN fp32) = A(M x K) @ B(N x K)^T,  bf16 inputs.
// CTA 128x128, BK=64, 8 warps (2x4), warp tile 64x32, m16n8k16.
// 3-stage cp.async pipeline, XOR-swizzled smem, ldmatrix fragment loads.
// epi: 0 = plain store, 1 = softplus(acc + bias[col]).
// ============================================================================
#define BM 128
#define BN 128
#define BKB 64
#define TILE_BYTES (BM * BKB * 2)    // 16384 per operand
#define STG_BYTES  (2 * TILE_BYTES)  // 32768 per stage
#define NSTAGE 3
#define GEMM_SMEM (NSTAGE * STG_BYTES)   // 98304

__device__ __forceinline__ void load_tile_bf(
    const __nv_bfloat16* __restrict__ A, const __nv_bfloat16* __restrict__ B,
    int K, int brow, int bcol, int k0, char* sA, char* sB, int tid)
{
#pragma unroll
    for (int i = 0; i < 4; i++) {             // A: 128 rows x 8 chunks of 16B
        int ch = tid + i * 256;
        int r = ch >> 3, c = ch & 7;
        const __nv_bfloat16* g = A + (size_t)(brow + r) * K + k0 + c * 8;
        cp_async16(smem_u32(sA + r * 128 + ((c ^ (r & 7)) << 4)), g);
    }
#pragma unroll
    for (int i = 0; i < 4; i++) {             // B: 128 rows x 8 chunks of 16B
        int ch = tid + i * 256;
        int r = ch >> 3, c = ch & 7;
        const __nv_bfloat16* g = B + (size_t)(bcol + r) * K + k0 + c * 8;
        cp_async16(smem_u32(sB + r * 128 + ((c ^ (r & 7)) << 4)), g);
    }
}

__global__ __launch_bounds__(256) void bf16_gemm_kernel(
    int M, int N, int K,
    const __nv_bfloat16* __restrict__ A, const __nv_bfloat16* __restrict__ B,
    float* __restrict__ C, const float* __restrict__ bias, int epi)
{
    extern __shared__ char smem_raw[];
    const int tid  = threadIdx.x;
    const int wid  = tid >> 5;
    const int lane = tid & 31;
    const int wm   = (wid >> 2) * 64;
    const int wn   = (wid & 3) * 32;
    const int brow = blockIdx.y * BM;
    const int bcol = blockIdx.x * BN;

    float acc[4][4][4];
#pragma unroll
    for (int mi = 0; mi < 4; mi++)
#pragma unroll
        for (int ni = 0; ni < 4; ni++)
#pragma unroll
            for (int c = 0; c < 4; c++) acc[mi][ni][c] = 0.f;

    const int KT = K / BKB;

    load_tile_bf(A, B, K, brow, bcol, 0, smem_raw, smem_raw + TILE_BYTES, tid);
    cp_commit();
    load_tile_bf(A, B, K, brow, bcol, BKB,
                 smem_raw + STG_BYTES, smem_raw + STG_BYTES + TILE_BYTES, tid);
    cp_commit();

    for (int kt = 0; kt < KT; kt++) {
        if (kt + 1 < KT) cp_wait<1>(); else cp_wait<0>();
        __syncthreads();

        if (kt + 2 < KT) {
            int slot = (kt + 2) % NSTAGE;
            load_tile_bf(A, B, K, brow, bcol, (kt + 2) * BKB,
                         smem_raw + slot * STG_BYTES,
                         smem_raw + slot * STG_BYTES + TILE_BYTES, tid);
            cp_commit();
        }

        char* sA = smem_raw + (kt % NSTAGE) * STG_BYTES;
        char* sB = sA + TILE_BYTES;
        uint32_t aBase = smem_u32(sA);
        uint32_t bBase = smem_u32(sB);

#pragma unroll
        for (int kk = 0; kk < 4; kk++) {
            uint32_t a[4][4], b[2][4];
#pragma unroll
            for (int mi = 0; mi < 4; mi++) {
                int R  = wm + mi * 16 + (lane & 15);
                int Cc = kk * 2 + (lane >> 4);
                LDSM_X4(a[mi], aBase + R * 128 + ((Cc ^ (R & 7)) << 4));
            }
#pragma unroll
            for (int p = 0; p < 2; p++) {
                int R  = wn + p * 16 + (lane & 7) + ((lane >> 4) << 3);
                int Cc = kk * 2 + ((lane >> 3) & 1);
                LDSM_X4(b[p], bBase + R * 128 + ((Cc ^ (R & 7)) << 4));
            }
#pragma unroll
            for (int mi = 0; mi < 4; mi++)
#pragma unroll
                for (int ni = 0; ni < 4; ni++) {
                    uint32_t b0 = b[ni >> 1][(ni & 1) * 2];
                    uint32_t b1 = b[ni >> 1][(ni & 1) * 2 + 1];
                    MMA_BF16(acc[mi][ni], a[mi], b0, b1);
                }
        }
    }

    // ------------------------------ epilogue -------------------------------
    const int erow = lane >> 2;
    const int ecol = (lane & 3) * 2;
#pragma unroll
    for (int mi = 0; mi < 4; mi++) {
#pragma unroll
        for (int ni = 0; ni < 4; ni++) {
            int row = brow + wm + mi * 16 + erow;
            int col = bcol + wn + ni * 8 + ecol;
            if (epi == 0) {
                *(float2*)&C[(size_t)row * N + col] =
                    make_float2(acc[mi][ni][0], acc[mi][ni][1]);
                *(float2*)&C[(size_t)(row + 8) * N + col] =
                    make_float2(acc[mi][ni][2], acc[mi][ni][3]);
            } else {
                float b0 = bias[col], b1 = bias[col + 1];
                float v[4] = {acc[mi][ni][0] + b0, acc[mi][ni][1] + b1,
                              acc[mi][ni][2] + b0, acc[mi][ni][3] + b1};
#pragma unroll
                for (int q = 0; q < 4; q++)
                    v[q] = (v[q] > 20.f) ? v[q] : log1pf(expf(v[q]));
                *(float2*)&C[(size_t)row * N + col] = make_float2(v[0], v[1]);
                *(float2*)&C[(size_t)(row + 8) * N + col] = make_float2(v[2], v[3]);
            }
        }
    }
}

// ============================================================================
// bf16x3 conversion pre-passes
// ============================================================================
// A-side: src (M x K fp32, row stride ld) -> dst (M x 3K bf16): [ah | al | ah]
// K must be a power of two (passed as kshift).
__global__ __launch_bounds__(256) void convA_bf3(
    const float* __restrict__ src, __nv_bfloat16* __restrict__ dst,
    int ld, int kshift)
{
    int idx = blockIdx.x * 256 + threadIdx.x;
    int K = 1 << kshift;
    int m = idx >> kshift;
    int k = idx & (K - 1);
    float v = src[(size_t)m * ld + k];
    __nv_bfloat16 h = __float2bfloat16(v);
    __nv_bfloat16 l = __float2bfloat16(v - __bfloat162float(h));
    size_t b = (size_t)m * (3 * K);
    dst[b + k] = h;
    dst[b + K + k] = l;
    dst[b + 2 * K + k] = h;
}

// B-side (transpose): src (K x N fp32) -> dst (N x 3K bf16): [bh | bh | bl]
__global__ __launch_bounds__(256) void convB_bf3(
    const float* __restrict__ src, __nv_bfloat16* __restrict__ dst, int K, int N)
{
    __shared__ float t[32][33];
    int k0 = blockIdx.y * 32, n0 = blockIdx.x * 32;
    int tx = threadIdx.x, ty = threadIdx.y;    // (32, 8)
#pragma unroll
    for (int i = 0; i < 4; i++)
        t[ty + 8 * i][tx] = src[(size_t)(k0 + ty + 8 * i) * N + n0 + tx];
    __syncthreads();
#pragma unroll
    for (int i = 0; i < 4; i++) {
        int n = n0 + ty + 8 * i;
        int k = k0 + tx;
        float v = t[tx][ty + 8 * i];
        __nv_bfloat16 h = __float2bfloat16(v);
        __nv_bfloat16 l = __float2bfloat16(v - __bfloat162float(h));
        size_t b = (size_t)n * (3 * K);
        dst[b + k] = h;
        dst[b + K + k] = h;
        dst[b + 2 * K + k] = l;
    }
}

// ============================================================================
// causal depthwise conv1d (K=4) + bias + silu.  xin -> u
// ============================================================================
__global__ __launch_bounds__(256) void conv_silu_kernel(
    const float* __restrict__ cw, const float* __restrict__ cb)
{
    int idx = blockIdx.x * 256 + threadIdx.x;
    int d   = idx & (DI - 1);
    int row = idx >> 11;
    int t   = row & (LSEQ - 1);

    float acc = cb[d];
#pragma unroll
    for (int k = 0; k < 4; k++) {
        int tt = t - 3 + k;
        if (tt >= 0)
            acc += __ldg(&cw[d * 4 + k]) * g_xr[(size_t)(row - 3 + k) * (2 * DI) + d];
    }
    g_u[idx] = acc / (1.f + expf(-acc));
}

// ============================================================================
// x_dbl = u @ W_x   (4096 x 2048 x 96)
// ============================================================================
__global__ __launch_bounds__(256) void gemm_xdbl_kernel(const float* __restrict__ Wx)
{
    __shared__ float As[16][64];
    __shared__ float Bs[16][NPROJ];

    const int tid  = threadIdx.x;
    const int brow = blockIdx.x * 64;
    const int ar = tid >> 2;
    const int ak = (tid & 3) * 4;
    const int trow = (tid >> 4) * 4;
    const int tcol = (tid & 15) * 6;

    float acc[4][6];
#pragma unroll
    for (int i = 0; i < 4; i++)
#pragma unroll
        for (int j = 0; j < 6; j++) acc[i][j] = 0.f;

    for (int k0 = 0; k0 < DI; k0 += 16) {
        {
            float4 v = *(const float4*)&g_u[(size_t)(brow + ar) * DI + k0 + ak];
            As[ak + 0][ar] = v.x;
            As[ak + 1][ar] = v.y;
            As[ak + 2][ar] = v.z;
            As[ak + 3][ar] = v.w;
        }
#pragma unroll
        for (int i = 0; i < 6; i++) {
            int idx = tid + i * 256;
            int r = idx / NPROJ;
            int c = idx - r * NPROJ;
            Bs[r][c] = Wx[(size_t)(k0 + r) * NPROJ + c];
        }
        __syncthreads();

#pragma unroll
        for (int k = 0; k < 16; k++) {
            float ra[4], rb[6];
#pragma unroll
            for (int i = 0; i < 4; i++) ra[i] = As[k][trow + i];
#pragma unroll
            for (int j = 0; j < 6; j++) rb[j] = Bs[k][tcol + j];
#pragma unroll
            for (int i = 0; i < 4; i++)
#pragma unroll
                for (int j = 0; j < 6; j++) acc[i][j] += ra[i] * rb[j];
        }
        __syncthreads();
    }

#pragma unroll
    for (int i = 0; i < 4; i++)
#pragma unroll
        for (int j = 0; j < 6; j++)
            g_xdbl[(size_t)(brow + trow + i) * NPROJ + tcol + j] = acc[i][j];
}

// ============================================================================
// selective scan, fused with  y = (scan + u*D) * silu(res).
// ============================================================================
#define TCHUNK 64
__global__ __launch_bounds__(128) void scan_kernel(
    const float* __restrict__ A_log, const float* __restrict__ Dp)
{
    __shared__ float sB[TCHUNK][NST];
    __shared__ float sC[TCHUNK][NST];
    __shared__ float sDt[TCHUNK][32];
    __shared__ float sU[TCHUNK][32];
    __shared__ float sR[TCHUNK][32];

    const int b    = blockIdx.y;
    const int tid  = threadIdx.x;
    const int dloc = tid >> 2;
    const int ng   = tid & 3;
    const int n0   = ng * 4;
    const int d0   = blockIdx.x * 32;
    const int d    = d0 + dloc;

    float a2[4], h[4];
#pragma unroll
    for (int i = 0; i < 4; i++) {
        a2[i] = -expf(A_log[(size_t)d * NST + n0 + i]) * 1.44269504f;
        h[i] = 0.f;
    }
    const float Dv = Dp[d];

    for (int t0 = 0; t0 < LSEQ; t0 += TCHUNK) {
        for (int idx = tid; idx < TCHUNK * NST; idx += 128) {
            int tt = idx >> 4, n = idx & 15;
            size_t grow = (size_t)(b * LSEQ + t0 + tt) * NPROJ;
            sB[tt][n] = g_xdbl[grow + DTR + n];
            sC[tt][n] = g_xdbl[grow + DTR + NST + n];
        }
        for (int idx = tid; idx < TCHUNK * 32; idx += 128) {
            int tt = idx >> 5, dd = idx & 31;
            size_t base = (size_t)(b * LSEQ + t0 + tt) * DI + d0 + dd;
            sDt[tt][dd] = g_delta[base];
            sU[tt][dd]  = g_u[base];
            sR[tt][dd]  = g_xr[(size_t)(b * LSEQ + t0 + tt) * (2 * DI) + DI + d0 + dd];
        }
        __syncthreads();

        for (int tt = 0; tt < TCHUNK; tt++) {
            float dt_v = sDt[tt][dloc];
            float u_v  = sU[tt][dloc];
            float du   = dt_v * u_v;
            float yp = 0.f;
#pragma unroll
            for (int i = 0; i < 4; i++) {
                h[i] = fast_ex2(dt_v * a2[i]) * h[i] + du * sB[tt][n0 + i];
                yp += h[i] * sC[tt][n0 + i];
            }
            yp += __shfl_xor_sync(0xffffffffu, yp, 1);
            yp += __shfl_xor_sync(0xffffffffu, yp, 2);
            if (ng == 0) {
                float res = sR[tt][dloc];
                float sil = res / (1.f + expf(-res));
                g_y[(size_t)(b * LSEQ + t0 + tt) * DI + d] = (yp + u_v * Dv) * sil;
            }
        }
        __syncthreads();
    }
}

// ============================================================================
// host launch
// ============================================================================
extern "C" void kernel_launch(void* const* d_in, const int* in_sizes, int n_in,
                              void* d_out, int out_size)
{
    const float* x      = (const float*)d_in[0];
    const float* W_in   = (const float*)d_in[1];
    const float* conv_w = (const float*)d_in[2];
    const float* conv_b = (const float*)d_in[3];
    const float* W_x    = (const float*)d_in[4];
    const float* W_dt   = (const float*)d_in[5];
    const float* b_dt   = (const float*)d_in[6];
    const float* A_log  = (const float*)d_in[7];
    const float* Dp     = (const float*)d_in[8];
    const float* W_out  = (const float*)d_in[9];
    float* out          = (float*)d_out;

    float *p_xr, *p_y, *p_xdbl, *p_delta;
    cudaGetSymbolAddress((void**)&p_xr,    g_xr);
    cudaGetSymbolAddress((void**)&p_y,     g_y);
    cudaGetSymbolAddress((void**)&p_xdbl,  g_xdbl);
    cudaGetSymbolAddress((void**)&p_delta, g_delta);

    __nv_bfloat16 *p_xbf, *p_wibf, *p_ybf, *p_wobf, *p_xdblbf, *p_wdtbf;
    cudaGetSymbolAddress((void**)&p_xbf,    g_xbf);
    cudaGetSymbolAddress((void**)&p_wibf,   g_wibf);
    cudaGetSymbolAddress((void**)&p_ybf,    g_ybf);
    cudaGetSymbolAddress((void**)&p_wobf,   g_wobf);
    cudaGetSymbolAddress((void**)&p_xdblbf, g_xdblbf);
    cudaGetSymbolAddress((void**)&p_wdtbf,  g_wdtbf);

    cudaFuncSetAttribute(bf16_gemm_kernel,
                         cudaFuncAttributeMaxDynamicSharedMemorySize, GEMM_SMEM);

    // 0. expand x and W_in^T to bf16x3
    convA_bf3<<<(MROWS * DM) / 256, 256>>>(x, p_xbf, DM, 10);
    convB_bf3<<<dim3((2 * DI) / 32, DM / 32), dim3(32, 8)>>>(W_in, p_wibf, DM, 2 * DI);

    // 1. in-projection: (4096 x 3072) @ (3072 x 4096)
    bf16_gemm_kernel<<<dim3((2 * DI) / BN, MROWS / BM), 256, GEMM_SMEM>>>(
        MROWS, 2 * DI, 3 * DM, p_xbf, p_wibf, p_xr, nullptr, 0);

    // 2. causal depthwise conv + silu
    conv_silu_kernel<<<(MROWS * DI) / 256, 256>>>(conv_w, conv_b);

    // 3. x_dbl = u @ W_x
    gemm_xdbl_kernel<<<MROWS / 64, 256>>>(W_x);

    // 4. delta = softplus(x_dbl[:, :64] @ W_dt + b_dt)  (bf16x3, fused epi)
    convA_bf3<<<(MROWS * DTR) / 256, 256>>>(p_xdbl, p_xdblbf, NPROJ, 6);
    convB_bf3<<<dim3(DI / 32, DTR / 32), dim3(32, 8)>>>(W_dt, p_wdtbf, DTR, DI);
    bf16_gemm_kernel<<<dim3(DI / BN, MROWS / BM), 256, GEMM_SMEM>>>(
        MROWS, DI, 3 * DTR, p_xdblbf, p_wdtbf, p_delta, b_dt, 1);

    // 5. selective scan + gating epilogue (fused)
    scan_kernel<<<dim3(DI / 32, BATCH), 128>>>(A_log, Dp);

    // 5b. expand y and W_out^T to bf16x3
    convA_bf3<<<(MROWS * DI) / 256, 256>>>(p_y, p_ybf, DI, 11);
    convB_bf3<<<dim3(DM / 32, DI / 32), dim3(32, 8)>>>(W_out, p_wobf, DI, DM);

    // 6. out-projection: (4096 x 6144) @ (6144 x 1024)
    bf16_gemm_kernel<<<dim3(DM / BN, MROWS / BM), 256, GEMM_SMEM>>>(
        MROWS, DM, 3 * DI, p_ybf, p_wobf, out, nullptr, 0);
}